// round 8
// baseline (speedup 1.0000x reference)
#include <cuda_runtime.h>
#include <cuda_bf16.h>
#include <cstdint>

#define BATCH    2
#define T_SEQ    2048
#define D_MODEL  1024
#define N_HEADS  16
#define HD       64
#define BT       (BATCH * T_SEQ)     // 4096
#define QKV_N    (3 * D_MODEL)       // 3072
#define BIAS_COEF 0.1f

// Scratch (device globals: allocation-free per harness rules)
__device__ float g_qkv[(size_t)BT * QKV_N];     // [4096, 3072]  (tf32-rounded)
__device__ float g_att[(size_t)BT * D_MODEL];   // [4096, 1024]  (tf32-rounded)
__device__ float g_xt [(size_t)BT * D_MODEL];   // x rounded
__device__ float g_wq [(size_t)D_MODEL * QKV_N];
__device__ float g_wo [(size_t)D_MODEL * D_MODEL];

// ---------------------------------------------------------------------------
// helpers
// ---------------------------------------------------------------------------
__device__ __forceinline__ uint32_t f2tf32(float f) {
    uint32_t r;
    asm("cvt.rna.tf32.f32 %0, %1;" : "=r"(r) : "f"(f));
    return r;
}
__device__ __forceinline__ float rnd_tf32(float f) {
    return __uint_as_float(f2tf32(f));
}

__device__ __forceinline__ void mma_tf32(float c[4],
    uint32_t a0, uint32_t a1, uint32_t a2, uint32_t a3,
    uint32_t b0, uint32_t b1)
{
    asm volatile(
        "mma.sync.aligned.m16n8k8.row.col.f32.tf32.tf32.f32 "
        "{%0,%1,%2,%3}, {%4,%5,%6,%7}, {%8,%9}, {%0,%1,%2,%3};"
        : "+f"(c[0]), "+f"(c[1]), "+f"(c[2]), "+f"(c[3])
        : "r"(a0), "r"(a1), "r"(a2), "r"(a3), "r"(b0), "r"(b1));
}

__device__ __forceinline__ void cp16(uint32_t saddr, const void* g) {
    asm volatile("cp.async.cg.shared.global [%0], [%1], 16;" :: "r"(saddr), "l"(g));
}
__device__ __forceinline__ void cp_commit() {
    asm volatile("cp.async.commit_group;");
}
__device__ __forceinline__ void cp_wait1() {
    asm volatile("cp.async.wait_group 1;");
}
__device__ __forceinline__ void cp_wait0() {
    asm volatile("cp.async.wait_group 0;");
}
__device__ __forceinline__ uint32_t s2u(const void* p) {
    return (uint32_t)__cvta_generic_to_shared(p);
}

// ---------------------------------------------------------------------------
// Pre-round: out[i] = rna_tf32(in[i])
// ---------------------------------------------------------------------------
__global__ __launch_bounds__(256) void round_tf32_kernel(
    const float* __restrict__ in, float* __restrict__ out, int n4)
{
    for (int i = blockIdx.x * 256 + threadIdx.x; i < n4; i += gridDim.x * 256) {
        float4 v = *(const float4*)(in + (size_t)i * 4);
        v.x = rnd_tf32(v.x); v.y = rnd_tf32(v.y);
        v.z = rnd_tf32(v.z); v.w = rnd_tf32(v.w);
        *(float4*)(out + (size_t)i * 4) = v;
    }
}

// ---------------------------------------------------------------------------
// TF32 GEMM, cp.async double-buffered. Inputs must be pre-rounded to tf32.
// C = A[MxK] @ B[KxN] + bias.  Block 128x128, BK=32, 2 stages, 8 warps.
// (identical to the round-6 kernel that passed)
// ---------------------------------------------------------------------------
#define AS_STRIDE 44
#define BS_STRIDE 136
#define AS_STAGE (128 * AS_STRIDE)   // 5632 words
#define BS_STAGE (32 * BS_STRIDE)    // 4352 words
#define GEMM_SMEM_BYTES ((2 * AS_STAGE + 2 * BS_STAGE) * 4)   // 79872

__device__ __forceinline__ void gemm_load_stage(
    const float* __restrict__ Ag, const float* __restrict__ Bg,
    uint32_t* __restrict__ as, uint32_t* __restrict__ bs,
    int k0, int K, int N, int tid)
{
#pragma unroll
    for (int j = 0; j < 4; j++) {
        int i = tid + 256 * j;
        int row = i >> 3, c4 = (i & 7) << 2;
        cp16(s2u(&as[row * AS_STRIDE + c4]), Ag + (size_t)row * K + k0 + c4);
    }
#pragma unroll
    for (int j = 0; j < 4; j++) {
        int i = tid + 256 * j;
        int row = i >> 5, c4 = (i & 31) << 2;
        cp16(s2u(&bs[row * BS_STRIDE + c4]), Bg + (size_t)(k0 + row) * N + c4);
    }
    cp_commit();
}

__global__ __launch_bounds__(256) void gemm_tf32_db(
    const float* __restrict__ A, const float* __restrict__ B,
    const float* __restrict__ bias, float* __restrict__ C,
    int M, int N, int K, int round_out)
{
    extern __shared__ uint32_t smem[];
    uint32_t* As = smem;                    // [2][128*44]
    uint32_t* Bs = smem + 2 * AS_STAGE;     // [2][32*136]

    const int tid  = threadIdx.x;
    const int lane = tid & 31;
    const int warp = tid >> 5;
    const int wr = warp >> 2;
    const int wc = warp & 3;
    const int g = lane >> 2;
    const int t = lane & 3;
    const int bx = blockIdx.x, by = blockIdx.y;

    const float* Ag = A + (size_t)(by * 128) * K;
    const float* Bg = B + bx * 128;
    const int nK = K >> 5;

    float acc[4][4][4];
#pragma unroll
    for (int mt = 0; mt < 4; mt++)
#pragma unroll
        for (int nt = 0; nt < 4; nt++)
#pragma unroll
            for (int i = 0; i < 4; i++) acc[mt][nt][i] = 0.0f;

    gemm_load_stage(Ag, Bg, As, Bs, 0, K, N, tid);

    for (int it = 0; it < nK; it++) {
        int cur = it & 1;
        if (it + 1 < nK) {
            gemm_load_stage(Ag, Bg, As + (cur ^ 1) * AS_STAGE,
                            Bs + (cur ^ 1) * BS_STAGE, (it + 1) << 5, K, N, tid);
            cp_wait1();
        } else {
            cp_wait0();
        }
        __syncthreads();

        const uint32_t* as = As + cur * AS_STAGE;
        const uint32_t* bs = Bs + cur * BS_STAGE;
#pragma unroll
        for (int kk = 0; kk < 4; kk++) {
            uint32_t a[4][4], bf[4][2];
#pragma unroll
            for (int mt = 0; mt < 4; mt++) {
                int r = wr * 64 + mt * 16 + g;
                int c = kk * 8 + t;
                a[mt][0] = as[r * AS_STRIDE + c];
                a[mt][1] = as[(r + 8) * AS_STRIDE + c];
                a[mt][2] = as[r * AS_STRIDE + c + 4];
                a[mt][3] = as[(r + 8) * AS_STRIDE + c + 4];
            }
#pragma unroll
            for (int nt = 0; nt < 4; nt++) {
                int c = wc * 32 + nt * 8 + g;
                int r = kk * 8 + t;
                bf[nt][0] = bs[r * BS_STRIDE + c];
                bf[nt][1] = bs[(r + 4) * BS_STRIDE + c];
            }
#pragma unroll
            for (int mt = 0; mt < 4; mt++)
#pragma unroll
                for (int nt = 0; nt < 4; nt++)
                    mma_tf32(acc[mt][nt], a[mt][0], a[mt][1], a[mt][2], a[mt][3],
                             bf[nt][0], bf[nt][1]);
        }
        __syncthreads();
    }

    // Epilogue: bias + (optional tf32 round) + store
#pragma unroll
    for (int mt = 0; mt < 4; mt++) {
#pragma unroll
        for (int nt = 0; nt < 4; nt++) {
            int row = by * 128 + wr * 64 + mt * 16 + g;
            int col = bx * 128 + wc * 32 + nt * 8 + 2 * t;
            float b0 = bias[col], b1 = bias[col + 1];
            float r00 = acc[mt][nt][0] + b0, r01 = acc[mt][nt][1] + b1;
            float r10 = acc[mt][nt][2] + b0, r11 = acc[mt][nt][3] + b1;
            if (round_out) {
                r00 = rnd_tf32(r00); r01 = rnd_tf32(r01);
                r10 = rnd_tf32(r10); r11 = rnd_tf32(r11);
            }
            *(float2*)&C[(size_t)row * N + col] = make_float2(r00, r01);
            *(float2*)&C[(size_t)(row + 8) * N + col] = make_float2(r10, r11);
        }
    }
}

// ---------------------------------------------------------------------------
// Flash attention, tf32 MMA, cp.async double-buffered K/V/bias.
// Grid (T/128, H, B), 256 threads (8 warps), warp owns 16 q-rows.
// Each 64-key tile serves 128 q-rows -> K/V traffic halved vs 64-q blocks.
// qkv is pre-rounded to tf32 values, so raw bits are valid MMA operands.
// ---------------------------------------------------------------------------
#define KV_STRIDE 68                      // words; 272B, 16B-multiple
#define KV_STAGE  (2 * 64 * KV_STRIDE)    // K + V per stage = 8704 words
#define QROWS 128
#define ATTN_SMEM_U32 (2 * KV_STAGE + QROWS * KV_STRIDE + 2 * 64)
#define ATTN_SMEM_BYTES (ATTN_SMEM_U32 * 4)   // 104960 B

__device__ __forceinline__ void attn_prefetch(
    uint32_t* __restrict__ sm_base, float* __restrict__ bias_s,
    const float* __restrict__ kv_base, const float* __restrict__ bs_base,
    int kt, int s, int tid)
{
    uint32_t* Ksb = sm_base + s * KV_STAGE;
    uint32_t* Vsb = Ksb + 64 * KV_STRIDE;
    const float* kb = kv_base + (size_t)(kt * 64) * QKV_N;
    const float* vb = kb + D_MODEL;
#pragma unroll
    for (int j = 0; j < 4; j++) {
        int i = tid + 256 * j;
        int row = i >> 4, c4 = (i & 15) << 2;
        cp16(s2u(&Ksb[row * KV_STRIDE + c4]), kb + (size_t)row * QKV_N + c4);
        cp16(s2u(&Vsb[row * KV_STRIDE + c4]), vb + (size_t)row * QKV_N + c4);
    }
    if (tid < 16)
        cp16(s2u(&bias_s[s * 64 + tid * 4]), bs_base + kt * 64 + tid * 4);
    cp_commit();
}

__global__ __launch_bounds__(256) void attn_tf32(
    const float* __restrict__ qkv, const float* __restrict__ bscore,
    float* __restrict__ att)
{
    extern __shared__ uint32_t sm[];
    uint32_t* Ps = sm + 2 * KV_STAGE;                                // [128][68]
    float* bias_s = (float*)(sm + 2 * KV_STAGE + QROWS * KV_STRIDE); // [2][64]

    const int tid  = threadIdx.x;
    const int lane = tid & 31;
    const int w = tid >> 5;              // 0..7
    const int g = lane >> 2;
    const int t = lane & 3;
    const int qt = blockIdx.x, h = blockIdx.y, b = blockIdx.z;

    const float* kv_base = qkv + (size_t)b * T_SEQ * QKV_N + D_MODEL + h * HD;
    const float* bs_base = bscore + b * T_SEQ;

    // Preload Q fragments (pre-rounded values; x0.125 is exact pow2 scale)
    uint32_t qa[8][4];
    {
        const float* q0 = qkv + (size_t)(b * T_SEQ + qt * QROWS + w * 16 + g) * QKV_N + h * HD;
        const float* q8 = q0 + 8 * (size_t)QKV_N;
#pragma unroll
        for (int ks = 0; ks < 8; ks++) {
            int c = ks * 8 + t;
            qa[ks][0] = __float_as_uint(q0[c] * 0.125f);
            qa[ks][1] = __float_as_uint(q8[c] * 0.125f);
            qa[ks][2] = __float_as_uint(q0[c + 4] * 0.125f);
            qa[ks][3] = __float_as_uint(q8[c + 4] * 0.125f);
        }
    }

    float oacc[8][4];
#pragma unroll
    for (int nt = 0; nt < 8; nt++)
#pragma unroll
        for (int i = 0; i < 4; i++) oacc[nt][i] = 0.0f;
    float m0 = -1e30f, m1 = -1e30f, l0 = 0.0f, l1 = 0.0f;

    const int prow = w * 16 + g;     // 0..127
    const int NT = T_SEQ / 64;

    attn_prefetch(sm, bias_s, kv_base, bs_base, 0, 0, tid);

    for (int kt = 0; kt < NT; kt++) {
        int cur = kt & 1;
        if (kt + 1 < NT) {
            attn_prefetch(sm, bias_s, kv_base, bs_base, kt + 1, cur ^ 1, tid);
            cp_wait1();
        } else {
            cp_wait0();
        }
        __syncthreads();

        const uint32_t* Ksb = sm + cur * KV_STAGE;
        const uint32_t* Vsb = Ksb + 64 * KV_STRIDE;
        const float* bb = &bias_s[cur * 64];

        // S = Q K^T  (each warp: its 16 q-rows x 64 keys)
        float sacc[8][4];
#pragma unroll
        for (int nt = 0; nt < 8; nt++)
#pragma unroll
            for (int i = 0; i < 4; i++) sacc[nt][i] = 0.0f;
#pragma unroll
        for (int ks = 0; ks < 8; ks++) {
#pragma unroll
            for (int nt = 0; nt < 8; nt++) {
                int key = nt * 8 + g;
                int d = ks * 8 + t;
                uint32_t b0 = Ksb[key * KV_STRIDE + d];
                uint32_t b1 = Ksb[key * KV_STRIDE + d + 4];
                mma_tf32(sacc[nt], qa[ks][0], qa[ks][1], qa[ks][2], qa[ks][3], b0, b1);
            }
        }

        // bias add + tile max
        float mt0 = -1e30f, mt1 = -1e30f;
#pragma unroll
        for (int nt = 0; nt < 8; nt++) {
            float bb0 = bb[nt * 8 + 2 * t] * BIAS_COEF;
            float bb1 = bb[nt * 8 + 2 * t + 1] * BIAS_COEF;
            sacc[nt][0] += bb0; sacc[nt][1] += bb1;
            sacc[nt][2] += bb0; sacc[nt][3] += bb1;
            mt0 = fmaxf(mt0, fmaxf(sacc[nt][0], sacc[nt][1]));
            mt1 = fmaxf(mt1, fmaxf(sacc[nt][2], sacc[nt][3]));
        }
        mt0 = fmaxf(mt0, __shfl_xor_sync(0xFFFFFFFFu, mt0, 1));
        mt0 = fmaxf(mt0, __shfl_xor_sync(0xFFFFFFFFu, mt0, 2));
        mt1 = fmaxf(mt1, __shfl_xor_sync(0xFFFFFFFFu, mt1, 1));
        mt1 = fmaxf(mt1, __shfl_xor_sync(0xFFFFFFFFu, mt1, 2));

        float mn0 = fmaxf(m0, mt0), mn1 = fmaxf(m1, mt1);
        float c0 = __expf(m0 - mn0), c1 = __expf(m1 - mn1);
        m0 = mn0; m1 = mn1;

        float ls0 = 0.0f, ls1 = 0.0f;
#pragma unroll
        for (int nt = 0; nt < 8; nt++) {
            float p0 = __expf(sacc[nt][0] - mn0);
            float p1 = __expf(sacc[nt][1] - mn0);
            float p2 = __expf(sacc[nt][2] - mn1);
            float p3 = __expf(sacc[nt][3] - mn1);
            ls0 += p0 + p1; ls1 += p2 + p3;
            int col = nt * 8 + 2 * t;
            Ps[prow * KV_STRIDE + col] = f2tf32(p0);
            Ps[prow * KV_STRIDE + col + 1] = f2tf32(p1);
            Ps[(prow + 8) * KV_STRIDE + col] = f2tf32(p2);
            Ps[(prow + 8) * KV_STRIDE + col + 1] = f2tf32(p3);
            oacc[nt][0] *= c0; oacc[nt][1] *= c0;
            oacc[nt][2] *= c1; oacc[nt][3] *= c1;
        }
        ls0 += __shfl_xor_sync(0xFFFFFFFFu, ls0, 1);
        ls0 += __shfl_xor_sync(0xFFFFFFFFu, ls0, 2);
        ls1 += __shfl_xor_sync(0xFFFFFFFFu, ls1, 1);
        ls1 += __shfl_xor_sync(0xFFFFFFFFu, ls1, 2);
        l0 = l0 * c0 + ls0;
        l1 = l1 * c1 + ls1;
        __syncwarp(0xFFFFFFFFu);   // P rows are warp-private

        // O += P V
#pragma unroll
        for (int ks = 0; ks < 8; ks++) {
            int c = ks * 8 + t;
            uint32_t pa0 = Ps[prow * KV_STRIDE + c];
            uint32_t pa1 = Ps[(prow + 8) * KV_STRIDE + c];
            uint32_t pa2 = Ps[prow * KV_STRIDE + c + 4];
            uint32_t pa3 = Ps[(prow + 8) * KV_STRIDE + c + 4];
#pragma unroll
            for (int nt = 0; nt < 8; nt++) {
                int d = nt * 8 + g;
                int key = ks * 8 + t;
                uint32_t b0 = Vsb[key * KV_STRIDE + d];
                uint32_t b1 = Vsb[(key + 4) * KV_STRIDE + d];
                mma_tf32(oacc[nt], pa0, pa1, pa2, pa3, b0, b1);
            }
        }
        __syncthreads();   // protect buffer 'cur' before next iteration's prefetch
    }

    // Normalize + round + store (pre-rounded for out-proj consumption)
    float inv0 = 1.0f / l0, inv1 = 1.0f / l1;
    int row = b * T_SEQ + qt * QROWS + prow;
#pragma unroll
    for (int nt = 0; nt < 8; nt++) {
        int col = h * HD + nt * 8 + 2 * t;
        float2 v0 = make_float2(rnd_tf32(oacc[nt][0] * inv0), rnd_tf32(oacc[nt][1] * inv0));
        float2 v1 = make_float2(rnd_tf32(oacc[nt][2] * inv1), rnd_tf32(oacc[nt][3] * inv1));
        *(float2*)&att[(size_t)row * D_MODEL + col] = v0;
        *(float2*)&att[(size_t)(row + 8) * D_MODEL + col] = v1;
    }
}

// ---------------------------------------------------------------------------
// Launch
// ---------------------------------------------------------------------------
extern "C" void kernel_launch(void* const* d_in, const int* in_sizes, int n_in,
                              void* d_out, int out_size)
{
    const float* x      = (const float*)d_in[0];
    const float* bscore = (const float*)d_in[1];
    const float* W_qkv  = (const float*)d_in[2];
    const float* b_qkv  = (const float*)d_in[3];
    const float* W_out  = (const float*)d_in[4];
    const float* b_out  = (const float*)d_in[5];
    float* out = (float*)d_out;

    float *qkv_p, *att_p, *xt_p, *wq_p, *wo_p;
    cudaGetSymbolAddress((void**)&qkv_p, g_qkv);
    cudaGetSymbolAddress((void**)&att_p, g_att);
    cudaGetSymbolAddress((void**)&xt_p,  g_xt);
    cudaGetSymbolAddress((void**)&wq_p,  g_wq);
    cudaGetSymbolAddress((void**)&wo_p,  g_wo);

    (void)cudaFuncSetAttribute(attn_tf32,
        cudaFuncAttributeMaxDynamicSharedMemorySize, ATTN_SMEM_BYTES);
    (void)cudaFuncSetAttribute(gemm_tf32_db,
        cudaFuncAttributeMaxDynamicSharedMemorySize, GEMM_SMEM_BYTES);

    // 0) Pre-round inputs to tf32 values
    {
        int nx4 = BT * D_MODEL / 4;
        int nq4 = D_MODEL * QKV_N / 4;
        int no4 = D_MODEL * D_MODEL / 4;
        round_tf32_kernel<<<(nx4 + 255) / 256, 256>>>(x, xt_p, nx4);
        round_tf32_kernel<<<(nq4 + 255) / 256, 256>>>(W_qkv, wq_p, nq4);
        round_tf32_kernel<<<(no4 + 255) / 256, 256>>>(W_out, wo_p, no4);
    }

    // 1) QKV projection (round output for attention)
    gemm_tf32_db<<<dim3(QKV_N / 128, BT / 128), 256, GEMM_SMEM_BYTES>>>(
        xt_p, wq_p, b_qkv, qkv_p, BT, QKV_N, D_MODEL, 1);

    // 2) Flash attention (128 q-rows per block, 8 warps)
    attn_tf32<<<dim3(T_SEQ / QROWS, N_HEADS, BATCH), 256, ATTN_SMEM_BYTES>>>(
        qkv_p, bscore, att_p);

    // 3) Output projection (full fp32 output)
    gemm_tf32_db<<<dim3(D_MODEL / 128, BT / 128), 256, GEMM_SMEM_BYTES>>>(
        att_p, wo_p, b_out, out, BT, D_MODEL, D_MODEL, 0);
}